// round 3
// baseline (speedup 1.0000x reference)
#include <cuda_runtime.h>
#include <cstdint>

// CognitiveLorenzField: vL stays parallel to vL0, vJ stays in span{vL0,vJ0}.
// 500-step dynamics collapses to a scalar recurrence (a,b,c) driven by the
// Lorenz z. Output is rank-1/rank-2 expansion -> pure store bandwidth.
//
// R3: fill the machine. 1183 persistent writer CTAs (8/SM), table broadcast
// via shared memory, streaming float4 stores.

#define DIM       65536
#define STEPS     500
#define CHUNK     10
#define TCHUNKS   (STEPS / CHUNK)       // 50
#define IBLK      64                    // i-slices of 1024 floats
#define NTILES    (TCHUNKS * IBLK)      // 3200
#define NT        256
#define WRITERS   1183                  // + 1 producer = 1184 = 148*8 exactly
#define RBLK      64                    // reduction blocks

__device__ float4 g_tab[STEPS];         // (a, b, c, z) per step
__device__ int    g_flag[TCHUNKS];      // per-chunk ready flags
__device__ float  g_pP[RBLK], g_pQ[RBLK];

// ---- pre-kernel: per-block deterministic partial dots + flag reset ----
__global__ __launch_bounds__(NT)
void clf_pre(const float* __restrict__ vL, const float* __restrict__ vJ)
{
    const float4* vL4 = (const float4*)vL;
    const float4* vJ4 = (const float4*)vJ;
    int b = blockIdx.x;
    int k = b * NT + threadIdx.x;       // one float4 per thread, 1024 floats/block

    float4 l = vL4[k];
    float4 j = vJ4[k];
    float p = l.x * l.x + l.y * l.y + l.z * l.z + l.w * l.w;
    float q = l.x * j.x + l.y * j.y + l.z * j.z + l.w * j.w;

    #pragma unroll
    for (int off = 16; off > 0; off >>= 1) {
        p += __shfl_down_sync(0xffffffffu, p, off);
        q += __shfl_down_sync(0xffffffffu, q, off);
    }
    __shared__ float sp[8], sq[8];
    int wid = threadIdx.x >> 5, lid = threadIdx.x & 31;
    if (lid == 0) { sp[wid] = p; sq[wid] = q; }
    __syncthreads();
    if (threadIdx.x == 0) {
        float P = 0.0f, Q = 0.0f;
        #pragma unroll
        for (int i = 0; i < 8; i++) { P += sp[i]; Q += sq[i]; }
        g_pP[b] = P;
        g_pQ[b] = Q;
    }
    if (b == 0 && threadIdx.x < TCHUNKS)
        g_flag[threadIdx.x] = 0;        // re-arm for this graph replay
}

// ---- fused producer + persistent writers ----
__global__ __launch_bounds__(NT, 8)
void clf_main(const float* __restrict__ vL,
              const float* __restrict__ vJ,
              float* __restrict__ out)
{
    const float dt = 0.01f;

    if (blockIdx.x == 0) {
        // -------- producer (single thread scalar recurrence) --------
        if (threadIdx.x == 0) {
            float P = 0.0f, Q = 0.0f;
            #pragma unroll
            for (int i = 0; i < RBLK; i++) { P += g_pP[i]; Q += g_pQ[i]; }

            float x = 1.0f, y = 1.0f, z = 1.0f;
            float a = 1.0f, b = 0.0f, c = 1.0f;  // vL=a*vL0 ; vJ=b*vL0+c*vJ0
            float* out_z = out + 2ull * STEPS * DIM;

            for (int t = 0; t < STEPS; t++) {
                // Lorenz Euler step (reference op order)
                float dx = 10.0f * (y - x);
                float dy = x * (28.0f - z) - y;
                float dz = x * y - (float)(8.0 / 3.0) * z;
                x += dt * dx;
                y += dt * dy;
                z += dt * dz;
                float alpha = 1.0f + 0.5f * z;

                // scalarized vector dynamics
                float dot = a * (b * P + c * Q);
                float nsq = a * a * P + 1e-8f;
                float r   = __fdividef(dot, nsq);

                float an = a + dt * (alpha * ((r - 1.0f) * a) + 0.2f * a);
                float bn = b + dt * (alpha * (r * a - b) + 0.2f * (a - b));
                float cn = c + dt * (alpha * (-c) + 0.2f * (-c));
                a = an; b = bn; c = cn;

                g_tab[t] = make_float4(a, b, c, z);
                out_z[t] = z;

                if (((t + 1) % CHUNK) == 0) {
                    __threadfence();                       // publish table
                    ((volatile int*)g_flag)[t / CHUNK] = 1;
                }
            }
        }
        return;
    }

    // -------- persistent writers --------
    int w = blockIdx.x - 1;
    const float4* vL4 = (const float4*)vL;
    const float4* vJ4 = (const float4*)vJ;
    float4* outL4 = (float4*)out;
    float4* outJ4 = outL4 + (size_t)STEPS * (DIM / 4);

    __shared__ float4 s_tab[CHUNK];

    for (int tt = w; tt < NTILES; tt += WRITERS) {
        int chunk = tt >> 6;            // tile order is chunk-major
        int slice = tt & (IBLK - 1);
        int f4    = slice * NT + threadIdx.x;

        float4 l = __ldg(vL4 + f4);     // L2-hot after first touch
        float4 j = __ldg(vJ4 + f4);

        if (threadIdx.x == 0) {
            while (((volatile int*)g_flag)[chunk] == 0)
                __nanosleep(128);
            __threadfence();            // acquire
            #pragma unroll
            for (int u = 0; u < CHUNK; u++)
                s_tab[u] = __ldcg(&g_tab[chunk * CHUNK + u]);
        }
        __syncthreads();

        #pragma unroll
        for (int u = 0; u < CHUNK; u++) {
            int t = chunk * CHUNK + u;
            float4 s = s_tab[u];
            float a = s.x, b = s.y, c = s.z;

            float4 oL = make_float4(a * l.x, a * l.y, a * l.z, a * l.w);
            float4 oJ = make_float4(fmaf(b, l.x, c * j.x),
                                    fmaf(b, l.y, c * j.y),
                                    fmaf(b, l.z, c * j.z),
                                    fmaf(b, l.w, c * j.w));

            size_t base = (size_t)t * (DIM / 4) + f4;
            __stcs(&outL4[base], oL);   // streaming stores
            __stcs(&outJ4[base], oJ);
        }
        __syncthreads();                // protect s_tab reuse
    }
}

extern "C" void kernel_launch(void* const* d_in, const int* in_sizes, int n_in,
                              void* d_out, int out_size)
{
    const float* vL = (const float*)d_in[0];
    const float* vJ = (const float*)d_in[1];
    float* out = (float*)d_out;

    clf_pre<<<RBLK, NT>>>(vL, vJ);
    clf_main<<<1 + WRITERS, NT>>>(vL, vJ, out);
}

// round 4
// speedup vs baseline: 1.1816x; 1.1816x over previous
#include <cuda_runtime.h>
#include <cstdint>

// CognitiveLorenzField: vL stays parallel to vL0, vJ stays in span{vL0,vJ0}.
// 500-step dynamics collapses to a scalar recurrence (a,b,c) driven by the
// Lorenz z. Output is rank-1/rank-2 expansion -> pure store bandwidth.
//
// R4: revert to 592-writer config (R2 winner); 2 float4 per thread so each
// tile writes 8KB contiguous spans (fewer, fatter write streams).

#define DIM       65536
#define STEPS     500
#define CHUNK     10
#define TCHUNKS   (STEPS / CHUNK)       // 50
#define NSLICE    32                    // slices of 2048 floats (8KB)
#define NTILES    (TCHUNKS * NSLICE)    // 1600
#define NT        256
#define WRITERS   592                   // R2 winner: 4 CTA/SM
#define RBLK      64                    // reduction blocks

__device__ float4 g_tab[STEPS];         // (a, b, c, z) per step
__device__ int    g_flag[TCHUNKS];      // per-chunk ready flags
__device__ float  g_pP[RBLK], g_pQ[RBLK];

// ---- pre-kernel: per-block deterministic partial dots + flag reset ----
__global__ __launch_bounds__(NT)
void clf_pre(const float* __restrict__ vL, const float* __restrict__ vJ)
{
    const float4* vL4 = (const float4*)vL;
    const float4* vJ4 = (const float4*)vJ;
    int b = blockIdx.x;
    int k = b * NT + threadIdx.x;       // one float4 per thread, 1024 floats/block

    float4 l = vL4[k];
    float4 j = vJ4[k];
    float p = l.x * l.x + l.y * l.y + l.z * l.z + l.w * l.w;
    float q = l.x * j.x + l.y * j.y + l.z * j.z + l.w * j.w;

    #pragma unroll
    for (int off = 16; off > 0; off >>= 1) {
        p += __shfl_down_sync(0xffffffffu, p, off);
        q += __shfl_down_sync(0xffffffffu, q, off);
    }
    __shared__ float sp[8], sq[8];
    int wid = threadIdx.x >> 5, lid = threadIdx.x & 31;
    if (lid == 0) { sp[wid] = p; sq[wid] = q; }
    __syncthreads();
    if (threadIdx.x == 0) {
        float P = 0.0f, Q = 0.0f;
        #pragma unroll
        for (int i = 0; i < 8; i++) { P += sp[i]; Q += sq[i]; }
        g_pP[b] = P;
        g_pQ[b] = Q;
    }
    if (b == 0 && threadIdx.x < TCHUNKS)
        g_flag[threadIdx.x] = 0;        // re-arm for this graph replay
}

// ---- fused producer + persistent writers ----
__global__ __launch_bounds__(NT)
void clf_main(const float* __restrict__ vL,
              const float* __restrict__ vJ,
              float* __restrict__ out)
{
    const float dt = 0.01f;

    if (blockIdx.x == 0) {
        // -------- producer (single thread scalar recurrence) --------
        if (threadIdx.x == 0) {
            float P = 0.0f, Q = 0.0f;
            #pragma unroll
            for (int i = 0; i < RBLK; i++) { P += g_pP[i]; Q += g_pQ[i]; }

            float x = 1.0f, y = 1.0f, z = 1.0f;
            float a = 1.0f, b = 0.0f, c = 1.0f;  // vL=a*vL0 ; vJ=b*vL0+c*vJ0
            float* out_z = out + 2ull * STEPS * DIM;

            for (int t = 0; t < STEPS; t++) {
                // Lorenz Euler step (reference op order)
                float dx = 10.0f * (y - x);
                float dy = x * (28.0f - z) - y;
                float dz = x * y - (float)(8.0 / 3.0) * z;
                x += dt * dx;
                y += dt * dy;
                z += dt * dz;
                float alpha = 1.0f + 0.5f * z;

                // scalarized vector dynamics
                float dot = a * (b * P + c * Q);
                float nsq = a * a * P + 1e-8f;
                float r   = __fdividef(dot, nsq);

                float an = a + dt * (alpha * ((r - 1.0f) * a) + 0.2f * a);
                float bn = b + dt * (alpha * (r * a - b) + 0.2f * (a - b));
                float cn = c + dt * (alpha * (-c) + 0.2f * (-c));
                a = an; b = bn; c = cn;

                g_tab[t] = make_float4(a, b, c, z);
                out_z[t] = z;

                if (((t + 1) % CHUNK) == 0) {
                    __threadfence();                       // publish table
                    ((volatile int*)g_flag)[t / CHUNK] = 1;
                }
            }
        }
        return;
    }

    // -------- persistent writers (2 float4 per thread, 8KB tiles) --------
    int w = blockIdx.x - 1;
    const float4* vL4 = (const float4*)vL;
    const float4* vJ4 = (const float4*)vJ;
    float4* outL4 = (float4*)out;
    float4* outJ4 = outL4 + (size_t)STEPS * (DIM / 4);

    for (int tt = w; tt < NTILES; tt += WRITERS) {
        int chunk = tt / NSLICE;        // chunk-major tile order
        int slice = tt - chunk * NSLICE;
        int f0    = slice * (NT * 2) + threadIdx.x;  // two coalesced groups

        float4 l0 = __ldg(vL4 + f0);
        float4 j0 = __ldg(vJ4 + f0);
        float4 l1 = __ldg(vL4 + f0 + NT);
        float4 j1 = __ldg(vJ4 + f0 + NT);

        if (threadIdx.x == 0) {
            while (((volatile int*)g_flag)[chunk] == 0)
                __nanosleep(128);
            __threadfence();            // acquire
        }
        __syncthreads();

        #pragma unroll
        for (int u = 0; u < CHUNK; u++) {
            int t = chunk * CHUNK + u;
            float4 s = __ldcg(&g_tab[t]);   // warp-broadcast L2 hit
            float a = s.x, b = s.y, c = s.z;

            float4 oL0 = make_float4(a * l0.x, a * l0.y, a * l0.z, a * l0.w);
            float4 oL1 = make_float4(a * l1.x, a * l1.y, a * l1.z, a * l1.w);
            float4 oJ0 = make_float4(fmaf(b, l0.x, c * j0.x),
                                     fmaf(b, l0.y, c * j0.y),
                                     fmaf(b, l0.z, c * j0.z),
                                     fmaf(b, l0.w, c * j0.w));
            float4 oJ1 = make_float4(fmaf(b, l1.x, c * j1.x),
                                     fmaf(b, l1.y, c * j1.y),
                                     fmaf(b, l1.z, c * j1.z),
                                     fmaf(b, l1.w, c * j1.w));

            size_t base = (size_t)t * (DIM / 4) + f0;
            __stcs(&outL4[base],      oL0);
            __stcs(&outL4[base + NT], oL1);
            __stcs(&outJ4[base],      oJ0);
            __stcs(&outJ4[base + NT], oJ1);
        }
    }
}

extern "C" void kernel_launch(void* const* d_in, const int* in_sizes, int n_in,
                              void* d_out, int out_size)
{
    const float* vL = (const float*)d_in[0];
    const float* vJ = (const float*)d_in[1];
    float* out = (float*)d_out;

    clf_pre<<<RBLK, NT>>>(vL, vJ);
    clf_main<<<1 + WRITERS, NT>>>(vL, vJ, out);
}

// round 5
// speedup vs baseline: 1.3149x; 1.1128x over previous
#include <cuda_runtime.h>
#include <cstdint>

// CognitiveLorenzField: vL stays parallel to vL0, vJ stays in span{vL0,vJ0}.
// 500-step dynamics collapses to a scalar recurrence (a,b,c) driven by the
// Lorenz z. Output is rank-1/rank-2 expansion -> pure store bandwidth.
//
// R5: replace __threadfence + volatile publish/acquire with scoped
// st.release.gpu / ld.acquire.gpu on per-chunk flags. Otherwise identical
// to the R4/R2 structure (592 writers, 8KB tiles, __stcs streams).

#define DIM       65536
#define STEPS     500
#define CHUNK     10
#define TCHUNKS   (STEPS / CHUNK)       // 50
#define NSLICE    32                    // slices of 2048 floats (8KB)
#define NTILES    (TCHUNKS * NSLICE)    // 1600
#define NT        256
#define WRITERS   592                   // 4 CTA/SM
#define RBLK      64                    // reduction blocks

__device__ float4 g_tab[STEPS];         // (a, b, c, z) per step
__device__ int    g_flag[TCHUNKS];      // per-chunk ready flags
__device__ float  g_pP[RBLK], g_pQ[RBLK];

__device__ __forceinline__ void flag_release(int* p, int v) {
    asm volatile("st.release.gpu.global.s32 [%0], %1;" :: "l"(p), "r"(v) : "memory");
}
__device__ __forceinline__ int flag_acquire(const int* p) {
    int v;
    asm volatile("ld.acquire.gpu.global.s32 %0, [%1];" : "=r"(v) : "l"(p) : "memory");
    return v;
}

// ---- pre-kernel: per-block deterministic partial dots + flag reset ----
__global__ __launch_bounds__(NT)
void clf_pre(const float* __restrict__ vL, const float* __restrict__ vJ)
{
    const float4* vL4 = (const float4*)vL;
    const float4* vJ4 = (const float4*)vJ;
    int b = blockIdx.x;
    int k = b * NT + threadIdx.x;       // one float4 per thread, 1024 floats/block

    float4 l = vL4[k];
    float4 j = vJ4[k];
    float p = l.x * l.x + l.y * l.y + l.z * l.z + l.w * l.w;
    float q = l.x * j.x + l.y * j.y + l.z * j.z + l.w * j.w;

    #pragma unroll
    for (int off = 16; off > 0; off >>= 1) {
        p += __shfl_down_sync(0xffffffffu, p, off);
        q += __shfl_down_sync(0xffffffffu, q, off);
    }
    __shared__ float sp[8], sq[8];
    int wid = threadIdx.x >> 5, lid = threadIdx.x & 31;
    if (lid == 0) { sp[wid] = p; sq[wid] = q; }
    __syncthreads();
    if (threadIdx.x == 0) {
        float P = 0.0f, Q = 0.0f;
        #pragma unroll
        for (int i = 0; i < 8; i++) { P += sp[i]; Q += sq[i]; }
        g_pP[b] = P;
        g_pQ[b] = Q;
    }
    if (b == 0 && threadIdx.x < TCHUNKS)
        g_flag[threadIdx.x] = 0;        // re-arm for this graph replay
}

// ---- fused producer + persistent writers ----
__global__ __launch_bounds__(NT)
void clf_main(const float* __restrict__ vL,
              const float* __restrict__ vJ,
              float* __restrict__ out)
{
    const float dt = 0.01f;

    if (blockIdx.x == 0) {
        // -------- producer (single thread scalar recurrence) --------
        if (threadIdx.x == 0) {
            float P = 0.0f, Q = 0.0f;
            #pragma unroll
            for (int i = 0; i < RBLK; i++) { P += g_pP[i]; Q += g_pQ[i]; }

            float x = 1.0f, y = 1.0f, z = 1.0f;
            float a = 1.0f, b = 0.0f, c = 1.0f;  // vL=a*vL0 ; vJ=b*vL0+c*vJ0
            float* out_z = out + 2ull * STEPS * DIM;

            for (int t = 0; t < STEPS; t++) {
                // Lorenz Euler step (reference op order)
                float dx = 10.0f * (y - x);
                float dy = x * (28.0f - z) - y;
                float dz = x * y - (float)(8.0 / 3.0) * z;
                x += dt * dx;
                y += dt * dy;
                z += dt * dz;
                float alpha = 1.0f + 0.5f * z;

                // scalarized vector dynamics (keeps eps exactly as reference)
                float dot = a * (b * P + c * Q);
                float nsq = a * a * P + 1e-8f;
                float r   = __fdividef(dot, nsq);

                float an = a + dt * (alpha * ((r - 1.0f) * a) + 0.2f * a);
                float bn = b + dt * (alpha * (r * a - b) + 0.2f * (a - b));
                float cn = c + dt * (alpha * (-c) + 0.2f * (-c));
                a = an; b = bn; c = cn;

                __stcg(&g_tab[t], make_float4(a, b, c, z));  // L2-direct
                __stcg(&out_z[t], z);

                if (((t + 1) % CHUNK) == 0)
                    flag_release(&g_flag[t / CHUNK], 1);  // release: orders table stores
            }
        }
        return;
    }

    // -------- persistent writers (2 float4 per thread, 8KB tiles) --------
    int w = blockIdx.x - 1;
    const float4* vL4 = (const float4*)vL;
    const float4* vJ4 = (const float4*)vJ;
    float4* outL4 = (float4*)out;
    float4* outJ4 = outL4 + (size_t)STEPS * (DIM / 4);

    for (int tt = w; tt < NTILES; tt += WRITERS) {
        int chunk = tt / NSLICE;        // chunk-major tile order
        int slice = tt - chunk * NSLICE;
        int f0    = slice * (NT * 2) + threadIdx.x;  // two coalesced groups

        float4 l0 = __ldg(vL4 + f0);
        float4 j0 = __ldg(vJ4 + f0);
        float4 l1 = __ldg(vL4 + f0 + NT);
        float4 j1 = __ldg(vJ4 + f0 + NT);

        if (threadIdx.x == 0) {
            while (flag_acquire(&g_flag[chunk]) == 0)
                __nanosleep(128);
        }
        __syncthreads();                // broadcasts thread0's acquire to the CTA

        #pragma unroll
        for (int u = 0; u < CHUNK; u++) {
            int t = chunk * CHUNK + u;
            float4 s = __ldcg(&g_tab[t]);   // warp-broadcast L2 hit
            float a = s.x, b = s.y, c = s.z;

            float4 oL0 = make_float4(a * l0.x, a * l0.y, a * l0.z, a * l0.w);
            float4 oL1 = make_float4(a * l1.x, a * l1.y, a * l1.z, a * l1.w);
            float4 oJ0 = make_float4(fmaf(b, l0.x, c * j0.x),
                                     fmaf(b, l0.y, c * j0.y),
                                     fmaf(b, l0.z, c * j0.z),
                                     fmaf(b, l0.w, c * j0.w));
            float4 oJ1 = make_float4(fmaf(b, l1.x, c * j1.x),
                                     fmaf(b, l1.y, c * j1.y),
                                     fmaf(b, l1.z, c * j1.z),
                                     fmaf(b, l1.w, c * j1.w));

            size_t base = (size_t)t * (DIM / 4) + f0;
            __stcs(&outL4[base],      oL0);
            __stcs(&outL4[base + NT], oL1);
            __stcs(&outJ4[base],      oJ0);
            __stcs(&outJ4[base + NT], oJ1);
        }
    }
}

extern "C" void kernel_launch(void* const* d_in, const int* in_sizes, int n_in,
                              void* d_out, int out_size)
{
    const float* vL = (const float*)d_in[0];
    const float* vJ = (const float*)d_in[1];
    float* out = (float*)d_out;

    clf_pre<<<RBLK, NT>>>(vL, vJ);
    clf_main<<<1 + WRITERS, NT>>>(vL, vJ, out);
}